// round 7
// baseline (speedup 1.0000x reference)
#include <cuda_runtime.h>
#include <cuda_bf16.h>
#include <math_constants.h>

#define D 128
#define F 64
#define INV_T2 4.0f
#define NSEG 912            // 6 CTAs/SM x 152 SMs = one wave
#define RED_CTAS 512
#define CHUNK (NSEG / 8)
#define NMAX 262144

// ---------------- scratch (no allocations allowed) ----------------
__device__ __nv_bfloat16 g_ebf[NMAX * D];    // bf16 staged embeddings (64 MiB)
__device__ float  g_stage[NSEG * F * D];
__device__ int    g_cnt_stage[NSEG * F];
__device__ float  g_part[8 * F * D];
__device__ int    g_cnt_part[8 * F];
__device__ float  g_pinv[F];                 // 4 / p_norm
__device__ uint4  g_bfrag4[4 * 8 * 32];      // [sb][nt][lane] = {bx_h0,by_h0,bx_h1,by_h1}
__device__ double g_loss;
__device__ int    g_ticket;

// ---------------- helpers ----------------
__device__ __forceinline__ unsigned pack_bf16x2(float lo, float hi) {
    unsigned r;
    asm("cvt.rn.bf16x2.f32 %0, %1, %2;" : "=r"(r) : "f"(hi), "f"(lo));
    return r;
}

__device__ __forceinline__ void mma_bf16(float c[4],
                                         unsigned a0, unsigned a1, unsigned a2, unsigned a3,
                                         unsigned b0, unsigned b1) {
    asm volatile(
        "mma.sync.aligned.m16n8k16.row.col.f32.bf16.bf16.f32 "
        "{%0,%1,%2,%3}, {%4,%5,%6,%7}, {%8,%9}, {%0,%1,%2,%3};"
        : "+f"(c[0]), "+f"(c[1]), "+f"(c[2]), "+f"(c[3])
        : "r"(a0), "r"(a1), "r"(a2), "r"(a3), "r"(b0), "r"(b1));
}

__device__ __forceinline__ void ss_u32(float& ss, unsigned v) {
    __nv_bfloat162 h = *reinterpret_cast<__nv_bfloat162*>(&v);
    float2 f = __bfloat1622float2(h);
    ss += f.x * f.x + f.y * f.y;
}
__device__ __forceinline__ void ss_u4(float& ss, const uint4& v) {
    ss_u32(ss, v.x); ss_u32(ss, v.y); ss_u32(ss, v.z); ss_u32(ss, v.w);
}

// ---------------- K1: segment sums + bf16 staging ----------------
#define G 8
__global__ __launch_bounds__(128) void k_segsum(const float* __restrict__ emb,
                                                const int* __restrict__ fams,
                                                int n) {
    __shared__ float acc[F * D];
    __shared__ int   cnt[F];
    const int t = threadIdx.x;
    #pragma unroll
    for (int i = t; i < F * D; i += 128) acc[i] = 0.0f;
    if (t < F) cnt[t] = 0;
    __syncthreads();

    for (int i = blockIdx.x * 128 + t; i < n; i += gridDim.x * 128)
        atomicAdd(&cnt[fams[i]], 1);

    const int stride = gridDim.x;
    int r = blockIdx.x;

    int   cf[G]; float cv[G];
    int   nf[G]; float nv[G];

    if (r + (G - 1) * stride < n) {
        #pragma unroll
        for (int j = 0; j < G; j++) {
            cf[j] = fams[r + j * stride];
            cv[j] = emb[(size_t)(r + j * stride) * D + t];
        }
        int rn = r + G * stride;
        while (rn + (G - 1) * stride < n) {
            #pragma unroll
            for (int j = 0; j < G; j++) {
                nf[j] = fams[rn + j * stride];
                nv[j] = emb[(size_t)(rn + j * stride) * D + t];
            }
            // cv values have arrived; accumulate + stage as bf16 (no stall)
            #pragma unroll
            for (int j = 0; j < G; j++) acc[cf[j] * D + t] += cv[j];
            #pragma unroll
            for (int j = 0; j < G; j++)
                g_ebf[(size_t)(r + j * stride) * D + t] = __float2bfloat16(cv[j]);
            #pragma unroll
            for (int j = 0; j < G; j++) { cf[j] = nf[j]; cv[j] = nv[j]; }
            r = rn; rn += G * stride;
        }
        #pragma unroll
        for (int j = 0; j < G; j++) acc[cf[j] * D + t] += cv[j];
        #pragma unroll
        for (int j = 0; j < G; j++)
            g_ebf[(size_t)(r + j * stride) * D + t] = __float2bfloat16(cv[j]);
        r = rn;
    }
    for (; r < n; r += stride) {
        float v = emb[(size_t)r * D + t];
        acc[fams[r] * D + t] += v;
        g_ebf[(size_t)r * D + t] = __float2bfloat16(v);
    }

    __syncthreads();
    float* st = g_stage + (size_t)blockIdx.x * (F * D);
    #pragma unroll
    for (int i = t; i < F * D; i += 128) st[i] = acc[i];
    if (t < F) g_cnt_stage[blockIdx.x * F + t] = cnt[t];
}

// ---------------- K1b: reduce slabs -> 8 non-atomic partials ----------------
__global__ __launch_bounds__(128) void k_reduce() {
    const int bid = blockIdx.x;
    const int t   = threadIdx.x;
    if (bid < RED_CTAS) {
        const int dg = bid & 63;
        const int cg = bid >> 6;
        const int base = dg * 128 + t;
        const int c0 = cg * CHUNK, c1 = c0 + CHUNK;
        float s = 0.0f;
        int c = c0;
        for (; c + 7 < c1; c += 8) {
            float v0 = g_stage[(size_t)(c + 0) * (F * D) + base];
            float v1 = g_stage[(size_t)(c + 1) * (F * D) + base];
            float v2 = g_stage[(size_t)(c + 2) * (F * D) + base];
            float v3 = g_stage[(size_t)(c + 3) * (F * D) + base];
            float v4 = g_stage[(size_t)(c + 4) * (F * D) + base];
            float v5 = g_stage[(size_t)(c + 5) * (F * D) + base];
            float v6 = g_stage[(size_t)(c + 6) * (F * D) + base];
            float v7 = g_stage[(size_t)(c + 7) * (F * D) + base];
            s += ((v0 + v1) + (v2 + v3)) + ((v4 + v5) + (v6 + v7));
        }
        for (; c < c1; c++) s += g_stage[(size_t)c * (F * D) + base];
        g_part[cg * (F * D) + base] = s;
    } else {
        const int cg = bid - RED_CTAS;
        if (t < F) {
            int s = 0;
            const int c0 = cg * CHUNK, c1 = c0 + CHUNK;
            for (int c = c0; c < c1; c++) s += g_cnt_stage[c * F + t];
            g_cnt_part[cg * F + t] = s;
        }
    }
}

// ---------------- K2: protos, 4/p_norm, superblock-paired bf16 B-fragments ----------------
__global__ __launch_bounds__(256) void k_protos() {
    __shared__ float proto[8 * D];
    const int t  = threadIdx.x;
    const int nt = blockIdx.x;
    const int fbase = nt * 8;

    if (nt == 0 && t == 0) { g_loss = 0.0; g_ticket = 0; }

    #pragma unroll
    for (int i = t; i < 8 * D; i += 256) {
        int f = fbase + (i >> 7);
        int idx = f * D + (i & 127);
        float s = 0.0f;
        #pragma unroll
        for (int cg = 0; cg < 8; cg++) s += g_part[cg * (F * D) + idx];
        int c = 0;
        #pragma unroll
        for (int cg = 0; cg < 8; cg++) c += g_cnt_part[cg * F + f];
        proto[i] = s / fmaxf((float)c, 1.0f);
    }
    __syncthreads();

    {
        int lane = t & 31, w = t >> 5;
        float s = 0.0f;
        #pragma unroll
        for (int j = 0; j < 4; j++) {
            float v = proto[w * D + lane * 4 + j];
            s += v * v;
        }
        #pragma unroll
        for (int o = 16; o > 0; o >>= 1) s += __shfl_xor_sync(0xffffffffu, s, o);
        if (lane == 0) g_pinv[fbase + w] = INV_T2 / fmaxf(sqrtf(s), 1e-9f);
    }

    // Superblock layout: sb = kt>>1, h = kt&1; lane c covers k = sb*32 + 8c + 4h + {0..3}
    {
        int lane = t & 31;
        int kt   = t >> 5;
        int sb   = kt >> 1, h = kt & 1;
        int nl   = lane >> 2;
        int k0   = sb * 32 + (lane & 3) * 8 + h * 4;
        const float* p = proto + nl * D;
        uint2 b;
        b.x = pack_bf16x2(p[k0],     p[k0 + 1]);
        b.y = pack_bf16x2(p[k0 + 2], p[k0 + 3]);
        uint2* dst = reinterpret_cast<uint2*>(g_bfrag4);
        dst[((sb * 8 + nt) * 32 + lane) * 2 + h] = b;
    }
}

// ---------------- K3: fused dots + cosine + LSE + loss (+finalize), bf16 input ----------------
__global__ __launch_bounds__(256, 3) void k_loss(const int* __restrict__ fams,
                                                 int n, float* __restrict__ out) {
    __shared__ uint4 sB[4 * 8 * 32];   // 16 KB
    __shared__ float sPi[F];
    __shared__ float sRed[8];
    const int t = threadIdx.x;
    for (int i = t; i < 4 * 8 * 32; i += 256) sB[i] = g_bfrag4[i];
    if (t < F) sPi[t] = g_pinv[t];
    __syncthreads();

    const int lane = t & 31, wid = t >> 5;
    const int nwarps = gridDim.x * 8;
    const int nblocks = n >> 4;
    const int roff = (lane >> 2);
    const int coff = (lane & 3);
    const uint4* base = reinterpret_cast<const uint4*>(g_ebf);   // row = 16 uint4

    float lsum = 0.0f;

    int wb = blockIdx.x * 8 + wid;
    uint4 ea[4], eb[4];   // all 4 superblocks of both rows, loaded upfront

    if (wb < nblocks) {
        const uint4* p0 = base + (size_t)((wb << 4) + roff) * 16 + coff;
        #pragma unroll
        for (int sb = 0; sb < 4; sb++) { ea[sb] = p0[sb * 4]; eb[sb] = p0[128 + sb * 4]; }
    }

    while (wb < nblocks) {
        const int wbn = wb + nwarps;
        const bool has_next = wbn < nblocks;

        // fams for current wb: issued at top, consumed in epilogue (latency hidden)
        const int r = (wb << 4) + roff;
        const int f0 = fams[r];
        const int f1 = fams[r + 8];
        const uint4* np0 = has_next
            ? base + (size_t)((wbn << 4) + roff) * 16 + coff : base;

        float acc[8][4];
        #pragma unroll
        for (int nt = 0; nt < 8; nt++)
            #pragma unroll
            for (int j = 0; j < 4; j++) acc[nt][j] = 0.0f;

        float ss0 = 0.0f, ss1 = 0.0f;

        #pragma unroll
        for (int sb = 0; sb < 4; sb++) {
            ss_u4(ss0, ea[sb]);
            ss_u4(ss1, eb[sb]);
            #pragma unroll
            for (int nt = 0; nt < 8; nt++) {
                uint4 b = sB[(sb * 8 + nt) * 32 + lane];
                mma_bf16(acc[nt], ea[sb].x, eb[sb].x, ea[sb].y, eb[sb].y, b.x, b.y);
                mma_bf16(acc[nt], ea[sb].z, eb[sb].z, ea[sb].w, eb[sb].w, b.z, b.w);
            }
            if (has_next) {          // refill this superblock from next wb (WAR safe)
                ea[sb] = np0[sb * 4];
                eb[sb] = np0[128 + sb * 4];
            }
        }

        ss0 += __shfl_xor_sync(0xffffffffu, ss0, 1);
        ss0 += __shfl_xor_sync(0xffffffffu, ss0, 2);
        ss1 += __shfl_xor_sync(0xffffffffu, ss1, 1);
        ss1 += __shfl_xor_sync(0xffffffffu, ss1, 2);
        const float ie0 = rsqrtf(ss0);
        const float ie1 = rsqrtf(ss1);

        // logits in [-4,4] -> no max subtraction needed
        float pos0 = 0.0f, pos1 = 0.0f;
        float sum0 = 0.0f, sum1 = 0.0f;
        const int cbase = (lane & 3) * 2;

        #pragma unroll
        for (int nt = 0; nt < 8; nt++) {
            #pragma unroll
            for (int j = 0; j < 2; j++) {
                const int col = nt * 8 + cbase + j;
                const float w = sPi[col];
                float l0 = acc[nt][j]     * w * ie0;
                float l1 = acc[nt][2 + j] * w * ie1;
                sum0 += __expf(l0);
                sum1 += __expf(l1);
                if (col == f0) pos0 = l0;
                if (col == f1) pos1 = l1;
            }
        }
        pos0 += __shfl_xor_sync(0xffffffffu, pos0, 1);
        pos0 += __shfl_xor_sync(0xffffffffu, pos0, 2);
        pos1 += __shfl_xor_sync(0xffffffffu, pos1, 1);
        pos1 += __shfl_xor_sync(0xffffffffu, pos1, 2);
        sum0 += __shfl_xor_sync(0xffffffffu, sum0, 1);
        sum0 += __shfl_xor_sync(0xffffffffu, sum0, 2);
        sum1 += __shfl_xor_sync(0xffffffffu, sum1, 1);
        sum1 += __shfl_xor_sync(0xffffffffu, sum1, 2);

        if ((lane & 3) == 0) {
            lsum += (-0.5f * pos0 + __logf(sum0))
                  + (-0.5f * pos1 + __logf(sum1));
        }

        wb = wbn;
    }

    #pragma unroll
    for (int o = 16; o > 0; o >>= 1) lsum += __shfl_xor_sync(0xffffffffu, lsum, o);
    if (lane == 0) sRed[wid] = lsum;
    __syncthreads();
    if (t == 0) {
        float s = 0.0f;
        #pragma unroll
        for (int w = 0; w < 8; w++) s += sRed[w];
        atomicAdd(&g_loss, (double)s);
        __threadfence();
        int v = atomicAdd(&g_ticket, 1);
        if (v == (int)gridDim.x - 1) {
            double total = atomicAdd(&g_loss, 0.0);
            out[0] = (float)(total / (double)n);
        }
    }
}

// ---------------- launch ----------------
extern "C" void kernel_launch(void* const* d_in, const int* in_sizes, int n_in,
                              void* d_out, int out_size) {
    const float* emb  = (const float*)d_in[0];
    const int*   fams = (const int*)d_in[1];
    const int n = in_sizes[1];
    float* out = (float*)d_out;

    k_segsum<<<NSEG, 128>>>(emb, fams, n);
    k_reduce<<<RED_CTAS + 8, 128>>>();
    k_protos<<<8, 256>>>();
    k_loss<<<456, 256>>>(fams, n, out);
}